// round 1
// baseline (speedup 1.0000x reference)
#include <cuda_runtime.h>

// Problem constants
#define F       4096
#define TSTEPS  2048
#define ODIM    512

// Persistent kernel config
#define SROWS    13          // W rows pinned in SMEM per CTA
#define NTHREADS 256
#define NWARPS   (NTHREADS / 32)
#define SMEM_BYTES ((SROWS + 1) * F * sizeof(float))   // 13 rows of W + staged f = 229376 B

// Scratch: full feats history. Row 0 is never written -> stays zero (initial state).
__device__ float        g_feats[TSTEPS + 1][F];   // ~33.6 MB
__device__ unsigned int g_arrive;                  // ticket counter for grid barrier

// Wrap-safe, reset-free grid barrier (monotonic ticket counter).
__device__ __forceinline__ void grid_barrier(int nb) {
    __syncthreads();
    if (threadIdx.x == 0) {
        __threadfence();  // release: publish g_feats writes
        unsigned int ticket = atomicAdd(&g_arrive, 1u);
        unsigned int need   = ticket - (ticket % (unsigned)nb) + (unsigned)nb;
        while ((int)(*(volatile unsigned int*)&g_arrive - need) < 0) { /* spin */ }
        __threadfence();  // acquire
    }
    __syncthreads();
}

__global__ void __launch_bounds__(NTHREADS, 1)
rc_persistent_kernel(const float* __restrict__ x,
                     const float* __restrict__ W,
                     int nb)
{
    extern __shared__ float smem[];
    float* sW = smem;                 // [SROWS][F]
    float* sf = smem + SROWS * F;     // [F] staged current feats

    const int b    = blockIdx.x;
    const int tid  = threadIdx.x;
    const int lane = tid & 31;
    const int warp = tid >> 5;

    const int rstart = (b * F) / nb;
    const int rend   = ((b + 1) * F) / nb;
    const int nrows  = rend - rstart;
    const int nsm    = (nrows < SROWS) ? nrows : SROWS;

    // Pin first `nsm` of this CTA's W rows into SMEM (once).
    {
        const float4* src = (const float4*)(W + (size_t)rstart * F);
        float4*       dst = (float4*)sW;
        const int n4 = nsm * (F / 4);
        for (int i = tid; i < n4; i += NTHREADS) dst[i] = src[i];
    }
    __syncthreads();

    float4* sf4 = (float4*)sf;

    for (int t = 0; t < TSTEPS; ++t) {
        // Stage f^{(t)} (16 KB) from global into SMEM.
        const float4* fin = (const float4*)(g_feats[t]);
        for (int i = tid; i < F / 4; i += NTHREADS) sf4[i] = fin[i];
        __syncthreads();

        // Each warp computes row pairs (shares the staged-f SMEM reads).
        for (int r = warp * 2; r < nrows; r += NWARPS * 2) {
            const int  r1_valid = (r + 1) < nrows;
            const float4* w4a = (r < nsm)
                ? (const float4*)(sW + (size_t)r * F)
                : (const float4*)(W + (size_t)(rstart + r) * F);
            const float4* w4b = r1_valid
                ? ((r + 1 < nsm)
                    ? (const float4*)(sW + (size_t)(r + 1) * F)
                    : (const float4*)(W + (size_t)(rstart + r + 1) * F))
                : w4a;  // dummy (result discarded)

            float4 aa = make_float4(0.f, 0.f, 0.f, 0.f);
            float4 ab = make_float4(0.f, 0.f, 0.f, 0.f);
            #pragma unroll 8
            for (int k = lane; k < F / 4; k += 32) {
                const float4 fv = sf4[k];
                const float4 wa = w4a[k];
                aa.x = fmaf(wa.x, fv.x, aa.x);
                aa.y = fmaf(wa.y, fv.y, aa.y);
                aa.z = fmaf(wa.z, fv.z, aa.z);
                aa.w = fmaf(wa.w, fv.w, aa.w);
                const float4 wb = w4b[k];
                ab.x = fmaf(wb.x, fv.x, ab.x);
                ab.y = fmaf(wb.y, fv.y, ab.y);
                ab.z = fmaf(wb.z, fv.z, ab.z);
                ab.w = fmaf(wb.w, fv.w, ab.w);
            }
            float sa = (aa.x + aa.y) + (aa.z + aa.w);
            float sb = (ab.x + ab.y) + (ab.z + ab.w);
            #pragma unroll
            for (int off = 16; off; off >>= 1) {
                sa += __shfl_xor_sync(0xffffffffu, sa, off);
                sb += __shfl_xor_sync(0xffffffffu, sb, off);
            }
            if (lane == 0) {
                const int row = rstart + r;
                float y = sa + x[(size_t)row * TSTEPS + t];
                y = fminf(1.0f, fmaxf(-1.0f, y));
                g_feats[t + 1][row] = y;
                if (r1_valid) {
                    float y2 = sb + x[(size_t)(row + 1) * TSTEPS + t];
                    y2 = fminf(1.0f, fmaxf(-1.0f, y2));
                    g_feats[t + 1][row + 1] = y2;
                }
            }
        }
        grid_barrier(nb);
    }
}

// ---------------------------------------------------------------------------
// Readout: out[o, t] = sum_k w_out[o, k] * feats[t+1][k]
// Tiled fp32 SGEMM, 64x64 tiles, K-chunks of 32.
// ---------------------------------------------------------------------------
#define TO 64
#define TT 64
#define TK 32

__global__ void __launch_bounds__(256)
out_gemm_kernel(const float* __restrict__ wout, float* __restrict__ out)
{
    __shared__ float sw [TK][TO + 1];
    __shared__ float sfe[TK][TT + 1];

    const int o0  = blockIdx.y * TO;
    const int t0  = blockIdx.x * TT;
    const int tid = threadIdx.x;
    const int lk  = tid & 31;   // k index for loads
    const int lr  = tid >> 5;   // 0..7

    const int to = (tid & 15) * 4;   // 0..60
    const int tt = (tid >> 4) * 4;   // 0..60

    float acc[4][4] = {};

    for (int k0 = 0; k0 < F; k0 += TK) {
        #pragma unroll
        for (int i = 0; i < 8; ++i) {
            const int o = lr * 8 + i;
            sw[lk][o] = wout[(size_t)(o0 + o) * F + k0 + lk];
        }
        #pragma unroll
        for (int i = 0; i < 8; ++i) {
            const int tr = lr * 8 + i;
            sfe[lk][tr] = g_feats[t0 + tr + 1][k0 + lk];
        }
        __syncthreads();

        #pragma unroll
        for (int k = 0; k < TK; ++k) {
            float rw[4], rf[4];
            #pragma unroll
            for (int i = 0; i < 4; ++i) rw[i] = sw[k][to + i];
            #pragma unroll
            for (int j = 0; j < 4; ++j) rf[j] = sfe[k][tt + j];
            #pragma unroll
            for (int i = 0; i < 4; ++i)
                #pragma unroll
                for (int j = 0; j < 4; ++j)
                    acc[i][j] = fmaf(rw[i], rf[j], acc[i][j]);
        }
        __syncthreads();
    }

    #pragma unroll
    for (int i = 0; i < 4; ++i)
        #pragma unroll
        for (int j = 0; j < 4; ++j)
            out[(size_t)(o0 + to + i) * TSTEPS + t0 + tt + j] = acc[i][j];
}

extern "C" void kernel_launch(void* const* d_in, const int* in_sizes, int n_in,
                              void* d_out, int out_size)
{
    const float* x    = (const float*)d_in[0];   // [F, T]
    const float* W    = (const float*)d_in[1];   // [F, F]
    const float* wout = (const float*)d_in[2];   // [O, F]
    float* out = (float*)d_out;                  // [O, T]

    int nb = 0;
    cudaDeviceGetAttribute(&nb, cudaDevAttrMultiProcessorCount, 0);
    if (nb <= 0) nb = 148;

    cudaFuncSetAttribute(rc_persistent_kernel,
                         cudaFuncAttributeMaxDynamicSharedMemorySize,
                         (int)SMEM_BYTES);

    rc_persistent_kernel<<<nb, NTHREADS, SMEM_BYTES>>>(x, W, nb);

    dim3 g(TSTEPS / TT, ODIM / TO);
    out_gemm_kernel<<<g, 256>>>(wout, out);
}

// round 7
// speedup vs baseline: 1.1073x; 1.1073x over previous
#include <cuda_runtime.h>

#define F       4096
#define TSTEPS  2048
#define ODIM    512

// Persistent kernel partitioning: 147 CTAs x 28 rows (last CTA overlaps by
// duplicate-writing identical values -- benign).
#define NB      147
#define NR      28
#define R1      8             // rows pinned in registers (128 regs)
#define R2      14            // rows pinned in shared memory (224 KB)
#define RG      (NR - R1 - R2) // 6 rows streamed from L2

#define NTHREADS 256
#define NWARPS   8
// SMEM: R2 rows of W + 8x32 reduction buffer
#define SMEM_BYTES ((R2 * F + NWARPS * 32) * sizeof(float))

__device__ float        g_feats[TSTEPS + 1][F];   // row 0 stays zero (initial state)
__device__ unsigned int g_arrive;                  // monotonic ticket barrier

__device__ __forceinline__ void grid_barrier(int nb) {
    __syncthreads();
    if (threadIdx.x == 0) {
        __threadfence();
        unsigned int ticket = atomicAdd(&g_arrive, 1u);
        unsigned int need   = ticket - (ticket % (unsigned)nb) + (unsigned)nb;
        while ((int)(*(volatile unsigned int*)&g_arrive - need) < 0) { }
        __threadfence();
    }
    __syncthreads();
}

// Packed fp32x2 FMA (FFMA2 is PTX-only; ptxas never auto-fuses)
__device__ __forceinline__ void ffma2(unsigned long long& acc,
                                      unsigned long long a, unsigned long long b) {
    asm("fma.rn.f32x2 %0, %1, %2, %0;" : "+l"(acc) : "l"(a), "l"(b));
}
__device__ __forceinline__ float hadd2(unsigned long long a) {
    float x, y;
    asm("mov.b64 {%0, %1}, %2;" : "=f"(x), "=f"(y) : "l"(a));
    return x + y;
}

__global__ void __launch_bounds__(NTHREADS, 1)
rc_persistent_kernel(const float* __restrict__ x,
                     const float* __restrict__ W)
{
    extern __shared__ float smem[];
    float* sW  = smem;               // [R2][F]
    float* red = smem + R2 * F;      // [NWARPS][32]

    const int tid  = threadIdx.x;
    const int lane = tid & 31;
    const int warp = tid >> 5;
    const int b    = blockIdx.x;
    const int rstart = (b * NR > F - NR) ? (F - NR) : (b * NR);

    // This lane owns 16 columns: c0 + j*128, j = 0..3 (one float4 each).
    const int c0 = warp * 512 + lane * 4;

    // --- Pin R1 rows of W in registers (as packed f32x2 pairs) ---
    unsigned long long wrf[R1][8];
    #pragma unroll
    for (int r = 0; r < R1; ++r) {
        #pragma unroll
        for (int j = 0; j < 4; ++j) {
            ulonglong2 wv = *(const ulonglong2*)(W + (size_t)(rstart + r) * F + c0 + j * 128);
            wrf[r][2 * j]     = wv.x;
            wrf[r][2 * j + 1] = wv.y;
        }
    }
    // --- Pin R2 rows of W in SMEM ---
    {
        const float4* src = (const float4*)(W + (size_t)(rstart + R1) * F);
        float4*       dst = (float4*)sW;
        for (int i = tid; i < R2 * (F / 4); i += NTHREADS) dst[i] = src[i];
    }
    __syncthreads();

    for (int t = 0; t < TSTEPS; ++t) {
        // Prefetch this step's x value for the row this thread finalizes.
        float xv = 0.0f;
        if (tid < NR) xv = x[(size_t)(rstart + tid) * TSTEPS + t];

        // Load f^{(t)} for this lane's 16 columns (packed pairs).
        unsigned long long fp[8];
        #pragma unroll
        for (int j = 0; j < 4; ++j) {
            ulonglong2 fv = *(const ulonglong2*)(g_feats[t] + c0 + j * 128);
            fp[2 * j]     = fv.x;
            fp[2 * j + 1] = fv.y;
        }

        float v[32];
        #pragma unroll
        for (int i = 0; i < 32; ++i) v[i] = 0.0f;

        // Register-resident rows
        #pragma unroll
        for (int r = 0; r < R1; ++r) {
            unsigned long long acc = 0ull;
            #pragma unroll
            for (int j = 0; j < 8; ++j) ffma2(acc, wrf[r][j], fp[j]);
            v[r] = hadd2(acc);
        }
        // SMEM-resident rows
        #pragma unroll
        for (int r = 0; r < R2; ++r) {
            unsigned long long acc = 0ull;
            #pragma unroll
            for (int j = 0; j < 4; ++j) {
                ulonglong2 wv = *(const ulonglong2*)(sW + r * F + c0 + j * 128);
                ffma2(acc, wv.x, fp[2 * j]);
                ffma2(acc, wv.y, fp[2 * j + 1]);
            }
            v[R1 + r] = hadd2(acc);
        }
        // L2-streamed rows
        #pragma unroll
        for (int r = 0; r < RG; ++r) {
            unsigned long long acc = 0ull;
            const float* wrow = W + (size_t)(rstart + R1 + R2 + r) * F + c0;
            #pragma unroll
            for (int j = 0; j < 4; ++j) {
                ulonglong2 wv = *(const ulonglong2*)(wrow + j * 128);
                ffma2(acc, wv.x, fp[2 * j]);
                ffma2(acc, wv.y, fp[2 * j + 1]);
            }
            v[R1 + R2 + r] = hadd2(acc);
        }

        // Butterfly reduce-scatter: lane l ends with this warp's total for row l.
        #pragma unroll
        for (int d = 16; d >= 1; d >>= 1) {
            const bool up = (lane & d) != 0;
            #pragma unroll
            for (int i = 0; i < d; ++i) {
                float mine   = up ? v[i + d] : v[i];
                float theirs = up ? v[i]     : v[i + d];
                float recv = __shfl_xor_sync(0xffffffffu, theirs, d);
                v[i] = mine + recv;
            }
        }
        red[warp * 32 + lane] = v[0];
        __syncthreads();

        if (tid < NR) {
            float s = red[tid];
            #pragma unroll
            for (int w = 1; w < NWARPS; ++w) s += red[w * 32 + tid];
            s += xv;
            s = fminf(1.0f, fmaxf(-1.0f, s));
            g_feats[t + 1][rstart + tid] = s;
        }
        grid_barrier(NB);
    }
}

// ---------------------------------------------------------------------------
// Readout GEMM: out[o, t] = sum_k w_out[o, k] * feats[t+1][k]
// ---------------------------------------------------------------------------
#define TO 64
#define TT 64
#define TK 32

__global__ void __launch_bounds__(256)
out_gemm_kernel(const float* __restrict__ wout, float* __restrict__ out)
{
    __shared__ float sw [TK][TO + 1];
    __shared__ float sfe[TK][TT + 1];

    const int o0  = blockIdx.y * TO;
    const int t0  = blockIdx.x * TT;
    const int tid = threadIdx.x;
    const int lk  = tid & 31;
    const int lr  = tid >> 5;

    const int to = (tid & 15) * 4;
    const int tt = (tid >> 4) * 4;

    float acc[4][4] = {};

    for (int k0 = 0; k0 < F; k0 += TK) {
        #pragma unroll
        for (int i = 0; i < 8; ++i) {
            const int o = lr * 8 + i;
            sw[lk][o] = wout[(size_t)(o0 + o) * F + k0 + lk];
        }
        #pragma unroll
        for (int i = 0; i < 8; ++i) {
            const int tr = lr * 8 + i;
            sfe[lk][tr] = g_feats[t0 + tr + 1][k0 + lk];
        }
        __syncthreads();

        #pragma unroll
        for (int k = 0; k < TK; ++k) {
            float rw[4], rf[4];
            #pragma unroll
            for (int i = 0; i < 4; ++i) rw[i] = sw[k][to + i];
            #pragma unroll
            for (int j = 0; j < 4; ++j) rf[j] = sfe[k][tt + j];
            #pragma unroll
            for (int i = 0; i < 4; ++i)
                #pragma unroll
                for (int j = 0; j < 4; ++j)
                    acc[i][j] = fmaf(rw[i], rf[j], acc[i][j]);
        }
        __syncthreads();
    }

    #pragma unroll
    for (int i = 0; i < 4; ++i)
        #pragma unroll
        for (int j = 0; j < 4; ++j)
            out[(size_t)(o0 + to + i) * TSTEPS + t0 + tt + j] = acc[i][j];
}

extern "C" void kernel_launch(void* const* d_in, const int* in_sizes, int n_in,
                              void* d_out, int out_size)
{
    const float* x    = (const float*)d_in[0];   // [F, T]
    const float* W    = (const float*)d_in[1];   // [F, F]
    const float* wout = (const float*)d_in[2];   // [O, F]
    float* out = (float*)d_out;                  // [O, T]

    cudaFuncSetAttribute(rc_persistent_kernel,
                         cudaFuncAttributeMaxDynamicSharedMemorySize,
                         (int)SMEM_BYTES);

    rc_persistent_kernel<<<NB, NTHREADS, SMEM_BYTES>>>(x, W);

    dim3 g(TSTEPS / TT, ODIM / TO);
    out_gemm_kernel<<<g, 256>>>(wout, out);
}

// round 9
// speedup vs baseline: 1.6279x; 1.4702x over previous
#include <cuda_runtime.h>

#define F       4096
#define TSTEPS  2048
#define ODIM    512

// Persistent kernel partitioning: 147 CTAs x 28 rows (last CTA overlaps by
// duplicate-writing identical values -- benign).
#define NB      147
#define NR      28
#define R1      8             // rows pinned in registers (128 regs)
#define R2      14            // rows pinned in shared memory (224 KB)
#define RG      (NR - R1 - R2) // 6 rows streamed from L2

#define NTHREADS 256
#define NWARPS   8
#define SMEM_BYTES ((R2 * F + NWARPS * 32) * sizeof(float))

__device__ float        g_feats[TSTEPS + 1][F];   // row 0 stays zero (initial state)
// One flag per CTA, padded to its own 128B line. Monotonic across graph replays.
__device__ unsigned int g_flag[NB * 32];

__device__ __forceinline__ void ffma2(unsigned long long& acc,
                                      unsigned long long a, unsigned long long b) {
    asm("fma.rn.f32x2 %0, %1, %2, %0;" : "+l"(acc) : "l"(a), "l"(b));
}
__device__ __forceinline__ float hadd2(unsigned long long a) {
    float x, y;
    asm("mov.b64 {%0, %1}, %2;" : "=f"(x), "=f"(y) : "l"(a));
    return x + y;
}

__global__ void rc_noop_kernel() {}

__global__ void __launch_bounds__(NTHREADS, 1)
rc_persistent_kernel(const float* __restrict__ x,
                     const float* __restrict__ W)
{
    extern __shared__ float smem[];
    float* sW  = smem;               // [R2][F]
    float* red = smem + R2 * F;      // [NWARPS][32]

    const int tid  = threadIdx.x;
    const int lane = tid & 31;
    const int warp = tid >> 5;
    const int b    = blockIdx.x;
    const int rstart = (b * NR > F - NR) ? (F - NR) : (b * NR);

    // Common base for the monotonic flags (all flags equal at launch start).
    const unsigned int fbase = *(volatile unsigned int*)&g_flag[b * 32];

    // This lane owns 16 columns: c0 + j*128, j = 0..3 (one float4 each).
    const int c0 = warp * 512 + lane * 4;

    // --- Pin R1 rows of W in registers (as packed f32x2 pairs) ---
    unsigned long long wrf[R1][8];
    #pragma unroll
    for (int r = 0; r < R1; ++r) {
        #pragma unroll
        for (int j = 0; j < 4; ++j) {
            ulonglong2 wv = *(const ulonglong2*)(W + (size_t)(rstart + r) * F + c0 + j * 128);
            wrf[r][2 * j]     = wv.x;
            wrf[r][2 * j + 1] = wv.y;
        }
    }
    // --- Pin R2 rows of W in SMEM ---
    {
        const float4* src = (const float4*)(W + (size_t)(rstart + R1) * F);
        float4*       dst = (float4*)sW;
        for (int i = tid; i < R2 * (F / 4); i += NTHREADS) dst[i] = src[i];
    }
    __syncthreads();

    for (int t = 0; t < TSTEPS; ++t) {
        // Prefetch this step's x value for the row this thread finalizes.
        float xv = 0.0f;
        if (tid < NR) xv = x[(size_t)(rstart + tid) * TSTEPS + t];

        // Load f^{(t)} for this lane's 16 columns (packed pairs).
        unsigned long long fp[8];
        #pragma unroll
        for (int j = 0; j < 4; ++j) {
            ulonglong2 fv = *(const ulonglong2*)(g_feats[t] + c0 + j * 128);
            fp[2 * j]     = fv.x;
            fp[2 * j + 1] = fv.y;
        }

        float v[32];
        #pragma unroll
        for (int i = 0; i < 32; ++i) v[i] = 0.0f;

        // Register-resident rows
        #pragma unroll
        for (int r = 0; r < R1; ++r) {
            unsigned long long acc = 0ull;
            #pragma unroll
            for (int j = 0; j < 8; ++j) ffma2(acc, wrf[r][j], fp[j]);
            v[r] = hadd2(acc);
        }
        // SMEM-resident rows
        #pragma unroll
        for (int r = 0; r < R2; ++r) {
            unsigned long long acc = 0ull;
            #pragma unroll
            for (int j = 0; j < 4; ++j) {
                ulonglong2 wv = *(const ulonglong2*)(sW + r * F + c0 + j * 128);
                ffma2(acc, wv.x, fp[2 * j]);
                ffma2(acc, wv.y, fp[2 * j + 1]);
            }
            v[R1 + r] = hadd2(acc);
        }
        // L2-streamed rows
        #pragma unroll
        for (int r = 0; r < RG; ++r) {
            unsigned long long acc = 0ull;
            const float* wrow = W + (size_t)(rstart + R1 + R2 + r) * F + c0;
            #pragma unroll
            for (int j = 0; j < 4; ++j) {
                ulonglong2 wv = *(const ulonglong2*)(wrow + j * 128);
                ffma2(acc, wv.x, fp[2 * j]);
                ffma2(acc, wv.y, fp[2 * j + 1]);
            }
            v[R1 + R2 + r] = hadd2(acc);
        }

        // Butterfly reduce-scatter: lane l ends with this warp's total for row l.
        #pragma unroll
        for (int d = 16; d >= 1; d >>= 1) {
            const bool up = (lane & d) != 0;
            #pragma unroll
            for (int i = 0; i < d; ++i) {
                float mine   = up ? v[i + d] : v[i];
                float theirs = up ? v[i]     : v[i + d];
                float recv = __shfl_xor_sync(0xffffffffu, theirs, d);
                v[i] = mine + recv;
            }
        }
        red[warp * 32 + lane] = v[0];
        __syncthreads();

        if (tid < NR) {
            float s = red[tid];
            #pragma unroll
            for (int w = 1; w < NWARPS; ++w) s += red[w * 32 + tid];
            s += xv;
            s = fminf(1.0f, fmaxf(-1.0f, s));
            g_feats[t + 1][rstart + tid] = s;
        }

        // ---- Distributed-flag grid barrier ----
        const unsigned int target = fbase + (unsigned)(t + 1);
        __syncthreads();   // all feats STGs happen-before tid0's release store
        if (tid == 0) {
            asm volatile("st.global.release.gpu.u32 [%0], %1;"
                         :: "l"(&g_flag[b * 32]), "r"(target) : "memory");
        }
        if (tid < NB) {
            unsigned int vfl;
            do {
                asm volatile("ld.global.acquire.gpu.u32 %0, [%1];"
                             : "=r"(vfl) : "l"(&g_flag[tid * 32]) : "memory");
            } while ((int)(vfl - target) < 0);
        }
        __syncthreads();   // acquire by pollers happens-before everyone's next loads
    }
}

// ---------------------------------------------------------------------------
// Readout GEMM: out[o, t] = sum_k w_out[o, k] * feats[t+1][k]
// Padding of 4 floats keeps rows 16B-aligned so compute reads are LDS.128
// (half-warp broadcast); tile stores take 8-way conflicts but are 8x rarer.
// ---------------------------------------------------------------------------
#define TO 64
#define TT 64
#define TK 32

__global__ void __launch_bounds__(256)
out_gemm_kernel(const float* __restrict__ wout, float* __restrict__ out)
{
    __shared__ float sw [TK][TO + 4];
    __shared__ float sfe[TK][TT + 4];

    const int o0  = blockIdx.y * TO;
    const int t0  = blockIdx.x * TT;
    const int tid = threadIdx.x;
    const int lk  = tid & 31;
    const int lr  = tid >> 5;

    const int to = (tid & 15) * 4;
    const int tt = (tid >> 4) * 4;

    float acc[4][4] = {};

    for (int k0 = 0; k0 < F; k0 += TK) {
        #pragma unroll
        for (int i = 0; i < 8; ++i) {
            const int o = lr * 8 + i;
            sw[lk][o] = wout[(size_t)(o0 + o) * F + k0 + lk];
        }
        #pragma unroll
        for (int i = 0; i < 8; ++i) {
            const int tr = lr * 8 + i;
            sfe[lk][tr] = g_feats[t0 + tr + 1][k0 + lk];
        }
        __syncthreads();

        #pragma unroll
        for (int k = 0; k < TK; ++k) {
            const float4 rw = *(const float4*)&sw [k][to];
            const float4 rf = *(const float4*)&sfe[k][tt];
            acc[0][0] = fmaf(rw.x, rf.x, acc[0][0]);
            acc[0][1] = fmaf(rw.x, rf.y, acc[0][1]);
            acc[0][2] = fmaf(rw.x, rf.z, acc[0][2]);
            acc[0][3] = fmaf(rw.x, rf.w, acc[0][3]);
            acc[1][0] = fmaf(rw.y, rf.x, acc[1][0]);
            acc[1][1] = fmaf(rw.y, rf.y, acc[1][1]);
            acc[1][2] = fmaf(rw.y, rf.z, acc[1][2]);
            acc[1][3] = fmaf(rw.y, rf.w, acc[1][3]);
            acc[2][0] = fmaf(rw.z, rf.x, acc[2][0]);
            acc[2][1] = fmaf(rw.z, rf.y, acc[2][1]);
            acc[2][2] = fmaf(rw.z, rf.z, acc[2][2]);
            acc[2][3] = fmaf(rw.z, rf.w, acc[2][3]);
            acc[3][0] = fmaf(rw.w, rf.x, acc[3][0]);
            acc[3][1] = fmaf(rw.w, rf.y, acc[3][1]);
            acc[3][2] = fmaf(rw.w, rf.z, acc[3][2]);
            acc[3][3] = fmaf(rw.w, rf.w, acc[3][3]);
        }
        __syncthreads();
    }

    #pragma unroll
    for (int i = 0; i < 4; ++i)
        #pragma unroll
        for (int j = 0; j < 4; ++j)
            out[(size_t)(o0 + to + i) * TSTEPS + t0 + tt + j] = acc[i][j];
}

extern "C" void kernel_launch(void* const* d_in, const int* in_sizes, int n_in,
                              void* d_out, int out_size)
{
    const float* x    = (const float*)d_in[0];   // [F, T]
    const float* W    = (const float*)d_in[1];   // [F, F]
    const float* wout = (const float*)d_in[2];   // [O, F]
    float* out = (float*)d_out;                  // [O, T]

    cudaFuncSetAttribute(rc_persistent_kernel,
                         cudaFuncAttributeMaxDynamicSharedMemorySize,
                         (int)SMEM_BYTES);

    // Launch pattern (4/call): noop, rc, gemm, noop  ->  ncu's "-s 5 -c 1"
    // (6th launch) lands on rc_persistent_kernel for profiling visibility.
    rc_noop_kernel<<<1, 32>>>();
    rc_persistent_kernel<<<NB, NTHREADS, SMEM_BYTES>>>(x, W);
    dim3 g(TSTEPS / TT, ODIM / TO);
    out_gemm_kernel<<<g, 256>>>(wout, out);
    rc_noop_kernel<<<1, 32>>>();
}